// round 17
// baseline (speedup 1.0000x reference)
#include <cuda_runtime.h>
#include <cstdint>

// ============================================================
// RSNN: out = LIF16(x @ W^T + b)/16,  M=32768, N=512, K=512 fp32
// Bit-exact fp32 GEMM (k-sequential FMA == reference rounding) on
// the FFMA2 pipe. R17: warp lane map 16x2 -> 8x4 (tx,ty) cuts
// distinct smem read traffic 576->384 B/warp/k; L1 pipe (90.5%)
// was the limiter, FFMA2 count unchanged.
// ============================================================

typedef unsigned int u32;
typedef unsigned long long ull;

#define KD 512
#define ND 512
#define MAXM 32768

__device__ float g_xt[(size_t)KD * MAXM];       // 64 MB  XT[k][m]
__device__ float g_wt[(size_t)KD * ND];         // 1 MB   WT[k][n]
__device__ float g_thr[7];                      // LIF count thresholds

__device__ __forceinline__ u32 smem_u32(const void* p) {
    u32 a;
    asm("{ .reg .u64 t; cvta.to.shared.u64 t, %1; cvt.u32.u64 %0, t; }" : "=r"(a) : "l"(p));
    return a;
}
__device__ __forceinline__ void cpa16(u32 dst, const float* src) {
    asm volatile("cp.async.cg.shared.global [%0], [%1], 16;" :: "r"(dst), "l"(src));
}
#define CP_COMMIT()  asm volatile("cp.async.commit_group;" ::: "memory")
#define CP_WAIT0()   asm volatile("cp.async.wait_group 0;" ::: "memory")

__device__ __forceinline__ void ffma2(ull& d, ull a, ull b) {
    asm("fma.rn.f32x2 %0, %1, %2, %3;" : "=l"(d) : "l"(a), "l"(b), "l"(d));
}
__device__ __forceinline__ ull pack_dup(float x) {
    ull r;
    u32 u = __float_as_uint(x);
    asm("mov.b64 %0, {%1, %1};" : "=l"(r) : "r"(u));
    return r;
}
__device__ __forceinline__ void unpack2(ull v, float& lo, float& hi) {
    u32 l, h;
    asm("mov.b64 {%0, %1}, %2;" : "=r"(l), "=r"(h) : "l"(v));
    lo = __uint_as_float(l);
    hi = __uint_as_float(h);
}

// ---------------- threshold init: bisect exact fp32 boundaries ----------------
__global__ void init_thr() {
    const int tt[7] = {1, 2, 3, 4, 5, 8, 16};
    int i = threadIdx.x;
    if (i >= 7) return;
    int t = tt[i];
    u32 lo = __float_as_uint(1.0f);
    u32 hi = __float_as_uint(4.0f);
    while (hi - lo > 1) {
        u32 mid = (lo + hi) >> 1;
        float cur = __uint_as_float(mid);
        float v = 0.0f;
        for (int s = 0; s < t; s++) v = fmaf(cur - v, 0.5f, v);
        if (v >= 1.0f) hi = mid; else lo = mid;
    }
    g_thr[i] = __uint_as_float(hi);
}

// closed-form LIF16 (counts/16), thresholds bit-equal to the 16-step loop
__device__ __forceinline__ float lif_fast(float cur, const float* c) {
    float cnt = (cur >= c[0]) ? 8.0f : 0.0f;
    cnt += (cur >= c[1]) ? 3.0f : 0.0f;
    cnt += (cur >= c[2]) ? 1.0f : 0.0f;
    cnt += (cur >= c[3]) ? 1.0f : 0.0f;
    cnt += (cur >= c[4]) ? 1.0f : 0.0f;
    cnt += (cur >= c[5]) ? 1.0f : 0.0f;
    cnt += (cur >= c[6]) ? 1.0f : 0.0f;
    return cnt * 0.0625f;
}

// ---------------- pre-pass 1: XT[k][m] = X[m][k] ----------------
__global__ void transpose_x(const float* __restrict__ X, int M, int K) {
    __shared__ float t[32][33];
    const int kb = blockIdx.x * 32, mb = blockIdx.y * 32;
    const int tx = threadIdx.x, ty = threadIdx.y;   // 32 x 8
#pragma unroll
    for (int i = 0; i < 4; i++)
        t[ty + 8 * i][tx] = X[(size_t)(mb + ty + 8 * i) * K + kb + tx];
    __syncthreads();
#pragma unroll
    for (int i = 0; i < 4; i++)
        g_xt[(size_t)(kb + ty + 8 * i) * M + mb + tx] = t[tx][ty + 8 * i];
}

// ---------------- pre-pass 2: WT[k][n] = W[n][k] ----------------
__global__ void transpose_w(const float* __restrict__ W, int N, int K) {
    __shared__ float t[32][33];
    const int kb = blockIdx.x * 32, nb = blockIdx.y * 32;
    const int tx = threadIdx.x, ty = threadIdx.y;   // 32 x 8
#pragma unroll
    for (int i = 0; i < 4; i++)
        t[ty + 8 * i][tx] = W[(size_t)(nb + ty + 8 * i) * K + kb + tx];
    __syncthreads();
#pragma unroll
    for (int i = 0; i < 4; i++)
        g_wt[(size_t)(kb + ty + 8 * i) * N + nb + tx] = t[tx][ty + 8 * i];
}

// ---------------- GEMM + LIF ----------------
#define BM 64
#define BN 128
#define BK 32
#define NST 2
#define A_ST (BK * BM * 4)          // 8192  (A stage: [k][m], rows 256B)
#define B_ST (BK * BN * 4)          // 16384 (B stage: [k][n], rows 512B)
#define STAGE (A_ST + B_ST)         // 24576
#define SM_TOTAL (NST * STAGE)      // 49152

__global__ void __launch_bounds__(128, 4)
gemm_lif(const float* __restrict__ bias, float* __restrict__ out, int M) {
    extern __shared__ char smem[];
    const u32 sb = smem_u32(smem);
    const int tid = threadIdx.x;
    const int n0 = blockIdx.x * BN;     // n fastest -> A tile shared in L2 by 4 CTAs
    const int m0 = blockIdx.y * BM;

    // loaders (128 threads), straight k-major layouts:
    const u32 adst = (tid >> 4) * 256 + (tid & 15) * 16;
    const u32 bdst = A_ST + (tid >> 5) * 512 + (tid & 31) * 16;
    const float* ai = g_xt + (size_t)(tid >> 4) * M + m0 + (tid & 15) * 4;
    const float* bi = g_wt + (size_t)(tid >> 5) * ND + n0 + (tid & 31) * 4;

    const int NCHUNK = KD / BK;                  // 16

    // prologue: stage 0
    {
#pragma unroll
        for (int r = 0; r < 4; r++)
            cpa16(sb + adst + r * 2048, ai + (size_t)(8 * r) * M);
#pragma unroll
        for (int r = 0; r < 8; r++)
            cpa16(sb + bdst + r * 2048, bi + (size_t)(4 * r) * ND);
        CP_COMMIT();
        ai += (size_t)BK * M;
        bi += (size_t)BK * ND;
    }

    ull acc[4][8];
#pragma unroll
    for (int i = 0; i < 4; i++)
#pragma unroll
        for (int j = 0; j < 8; j++) acc[i][j] = 0ull;

    // R17 lane map: per warp 8 tx x 4 ty (was 16 x 2) -> smem reads
    // B 256B + A 128B distinct per warp-k instead of 512B + 64B.
    const int wid = tid >> 5, lane = tid & 31;
    const int tx = ((wid & 1) << 3) | (lane & 7);      // 0..15
    const int ty = ((wid >> 1) << 2) | (lane >> 3);    // 0..7

    for (int c = 0; c < NCHUNK; c++) {
        CP_WAIT0();
        __syncthreads();

        if (c + 1 < NCHUNK) {
            u32 s = sb + ((c + 1) & 1) * STAGE;
#pragma unroll
            for (int r = 0; r < 4; r++)
                cpa16(s + adst + r * 2048, ai + (size_t)(8 * r) * M);
#pragma unroll
            for (int r = 0; r < 8; r++)
                cpa16(s + bdst + r * 2048, bi + (size_t)(4 * r) * ND);
            CP_COMMIT();
            ai += (size_t)BK * M;
            bi += (size_t)BK * ND;
        }

        const char* st = smem + (c & 1) * STAGE;
#pragma unroll
        for (int k = 0; k < BK; k++) {
            union { float4 v; ull u[2]; } a0, a1;
            a0.v = *reinterpret_cast<const float4*>(st + k * 256 + ty * 32);
            a1.v = *reinterpret_cast<const float4*>(st + k * 256 + ty * 32 + 16);
            ull ap[4] = { a0.u[0], a0.u[1], a1.u[0], a1.u[1] };

            const char* brow = st + A_ST + k * 512 + tx * 32;
            float4 b0 = *reinterpret_cast<const float4*>(brow);
            float4 b1 = *reinterpret_cast<const float4*>(brow + 16);
            ull bp[8] = { pack_dup(b0.x), pack_dup(b0.y), pack_dup(b0.z), pack_dup(b0.w),
                          pack_dup(b1.x), pack_dup(b1.y), pack_dup(b1.z), pack_dup(b1.w) };

#pragma unroll
            for (int i = 0; i < 4; i++)
#pragma unroll
                for (int j = 0; j < 8; j++)
                    ffma2(acc[i][j], ap[i], bp[j]);
        }
    }

    // ---- epilogue: bias + closed-form LIF + store ----
    float thr[7];
#pragma unroll
    for (int i = 0; i < 7; i++) thr[i] = g_thr[i];

    float4 bq0 = *reinterpret_cast<const float4*>(bias + n0 + tx * 8);
    float4 bq1 = *reinterpret_cast<const float4*>(bias + n0 + tx * 8 + 4);
    const float bv[8] = { bq0.x, bq0.y, bq0.z, bq0.w, bq1.x, bq1.y, bq1.z, bq1.w };

#pragma unroll
    for (int i = 0; i < 4; i++) {
        float lo[8], hi[8];
#pragma unroll
        for (int j = 0; j < 8; j++) unpack2(acc[i][j], lo[j], hi[j]);

        int m_lo = m0 + ty * 8 + 2 * i;
        float* p0 = out + (size_t)m_lo * ND + n0 + tx * 8;
        float* p1 = p0 + ND;

        float4 o;
        o.x = lif_fast(lo[0] + bv[0], thr); o.y = lif_fast(lo[1] + bv[1], thr);
        o.z = lif_fast(lo[2] + bv[2], thr); o.w = lif_fast(lo[3] + bv[3], thr);
        *reinterpret_cast<float4*>(p0) = o;
        o.x = lif_fast(lo[4] + bv[4], thr); o.y = lif_fast(lo[5] + bv[5], thr);
        o.z = lif_fast(lo[6] + bv[6], thr); o.w = lif_fast(lo[7] + bv[7], thr);
        *reinterpret_cast<float4*>(p0 + 4) = o;
        o.x = lif_fast(hi[0] + bv[0], thr); o.y = lif_fast(hi[1] + bv[1], thr);
        o.z = lif_fast(hi[2] + bv[2], thr); o.w = lif_fast(hi[3] + bv[3], thr);
        *reinterpret_cast<float4*>(p1) = o;
        o.x = lif_fast(hi[4] + bv[4], thr); o.y = lif_fast(hi[5] + bv[5], thr);
        o.z = lif_fast(hi[6] + bv[6], thr); o.w = lif_fast(hi[7] + bv[7], thr);
        *reinterpret_cast<float4*>(p1 + 4) = o;
    }
}

extern "C" void kernel_launch(void* const* d_in, const int* in_sizes, int n_in,
                              void* d_out, int out_size) {
    const float* x = (const float*)d_in[0];
    const float* W = (const float*)d_in[1];
    const float* b = (const float*)d_in[2];
    float* out = (float*)d_out;

    const int N = in_sizes[2];          // 512
    const int K = in_sizes[1] / N;      // 512
    const int M = in_sizes[0] / K;      // 32768

    dim3 tb(32, 8);
    dim3 tgx(K / 32, M / 32);
    transpose_x<<<tgx, tb>>>(x, M, K);
    dim3 tgw(K / 32, N / 32);
    transpose_w<<<tgw, tb>>>(W, N, K);
    init_thr<<<1, 32>>>();

    cudaFuncSetAttribute(gemm_lif, cudaFuncAttributeMaxDynamicSharedMemorySize, SM_TOTAL);
    dim3 grid(N / BN, M / BM);
    gemm_lif<<<grid, 128, SM_TOTAL>>>(b, out, M);
}